// round 1
// baseline (speedup 1.0000x reference)
#include <cuda_runtime.h>
#include <math.h>

// ---------------------------------------------------------------------------
// ShiftedWindowMSA: B=32, H=W=56, D=256, heads=8, head_dim=32, ws=4, shift=2
//   1) qkv = x @ W + b              (100352 x 256) @ (256 x 768)
//   2) windowed attention within 4x4 windows (shift folded into gather index)
// ---------------------------------------------------------------------------

#define M_TOTAL  100352          // 32 * 3136
#define K_DIM    256
#define N_DIM    768

// scratch for qkv (static device allocation is the sanctioned scratch path)
__device__ float g_qkv[(size_t)M_TOTAL * N_DIM];

// ---------------------------------------------------------------------------
// Kernel 1: SGEMM  C[M,768] = A[M,256] * B[256,768] + bias
// BM=128 BN=128 BK=8, 256 threads, 8x8 micro-tile per thread.
// M,N,K all divide tile sizes exactly -> no bounds checks.
// ---------------------------------------------------------------------------
__global__ __launch_bounds__(256) void qkv_gemm(
    const float* __restrict__ A, const float* __restrict__ B,
    const float* __restrict__ bias)
{
    constexpr int BM = 128, BN = 128, BK = 8, TM = 8, TN = 8;
    __shared__ float As[BK][BM];
    __shared__ float Bs[BK][BN];

    const int tid = threadIdx.x;
    const int tx  = tid & 15;          // 0..15
    const int ty  = tid >> 4;          // 0..15
    const int bm  = blockIdx.y * BM;
    const int bn  = blockIdx.x * BN;

    // A tile loader: thread -> (row 0..127, 4-float chunk 0/4)
    const int arow = tid >> 1;
    const int acol = (tid & 1) * 4;
    // B tile loader: thread -> (row 0..7, col chunk)
    const int brow = tid >> 5;
    const int bcol = (tid & 31) * 4;

    const float* Aptr = A + (size_t)(bm + arow) * K_DIM + acol;
    const float* Bptr = B + (size_t)brow * N_DIM + bn + bcol;

    float acc[TM][TN] = {};

    for (int k0 = 0; k0 < K_DIM; k0 += BK) {
        float4 av = *(const float4*)(Aptr + k0);
        float4 bv = *(const float4*)(Bptr + (size_t)k0 * N_DIM);
        __syncthreads();   // previous compute done before overwrite
        As[acol + 0][arow] = av.x;
        As[acol + 1][arow] = av.y;
        As[acol + 2][arow] = av.z;
        As[acol + 3][arow] = av.w;
        *(float4*)&Bs[brow][bcol] = bv;
        __syncthreads();

        #pragma unroll
        for (int k = 0; k < BK; k++) {
            float a[TM], bb[TN];
            #pragma unroll
            for (int i = 0; i < TM; i++) a[i] = As[k][ty * TM + i];
            #pragma unroll
            for (int j = 0; j < TN; j++) bb[j] = Bs[k][tx * TN + j];
            #pragma unroll
            for (int i = 0; i < TM; i++)
                #pragma unroll
                for (int j = 0; j < TN; j++)
                    acc[i][j] += a[i] * bb[j];
        }
    }

    // epilogue: add bias, write to g_qkv
    #pragma unroll
    for (int i = 0; i < TM; i++) {
        size_t row = (size_t)(bm + ty * TM + i);
        float* cp = g_qkv + row * N_DIM + bn + tx * TN;
        #pragma unroll
        for (int j = 0; j < TN; j += 4) {
            int nn = bn + tx * TN + j;
            float4 v;
            v.x = acc[i][j + 0] + bias[nn + 0];
            v.y = acc[i][j + 1] + bias[nn + 1];
            v.z = acc[i][j + 2] + bias[nn + 2];
            v.w = acc[i][j + 3] + bias[nn + 3];
            *(float4*)(cp + j) = v;
        }
    }
}

// ---------------------------------------------------------------------------
// Kernel 2: windowed attention. One block per (batch, window). 8 warps = 8 heads.
// qkv row layout of the 768 dim: (head 8, e 32, comp 3) -> off = h*96 + e*3 + comp
// Shift folded into gather/scatter row index: (wi*4+r+2)%56, (wj*4+c+2)%56.
// ---------------------------------------------------------------------------
#define HPAD 36          // padded head_dim stride in smem (bank spread + float4 ok)

__global__ __launch_bounds__(256) void win_attn(float* __restrict__ out)
{
    extern __shared__ float sm[];
    float* sQ = sm;                      // 8*16*36 = 4608
    float* sK = sQ + 8 * 16 * HPAD;
    float* sV = sK + 8 * 16 * HPAD;
    float* sP = sV + 8 * 16 * HPAD;      // 8*16*17 = 2176
    __shared__ int srow[16];

    const int tid = threadIdx.x;
    const int blk = blockIdx.x;
    const int b   = blk / 196;
    const int rem = blk % 196;
    const int wi  = rem / 14;
    const int wj  = rem % 14;

    if (tid < 16) {
        int r = tid >> 2, c = tid & 3;
        int y = (wi * 4 + r + 2) % 56;   // shifted source row
        int x = (wj * 4 + c + 2) % 56;   // shifted source col
        srow[tid] = b * 3136 + y * 56 + x;
    }
    __syncthreads();

    // load 16 tokens x 768, de-interleave into Q/K/V [h][t][e]
    for (int i = tid; i < 16 * 192; i += 256) {
        int t = i / 192, q4 = i % 192;
        float4 v = *(const float4*)(g_qkv + (size_t)srow[t] * N_DIM + q4 * 4);
        float vals[4] = {v.x, v.y, v.z, v.w};
        #pragma unroll
        for (int j = 0; j < 4; j++) {
            int f = q4 * 4 + j;
            int h = f / 96;
            int rr = f - h * 96;
            int e = rr / 3;
            int comp = rr - e * 3;
            int idx = h * (16 * HPAD) + t * HPAD + e;
            if (comp == 0)      sQ[idx] = vals[j];
            else if (comp == 1) sK[idx] = vals[j];
            else                sV[idx] = vals[j];
        }
    }
    __syncthreads();

    const int h = tid >> 5, lane = tid & 31;
    const float* Q = sQ + h * (16 * HPAD);
    const float* K = sK + h * (16 * HPAD);
    const float* V = sV + h * (16 * HPAD);
    float* P = sP + h * (16 * 17);
    const bool lastrow = (wi == 13), lastcol = (wj == 13);

    // scores: each lane computes 8 (t,s) entries
    #pragma unroll
    for (int p = 0; p < 8; p++) {
        int flat = lane * 8 + p;
        int t = flat >> 4, s = flat & 15;
        float acc = 0.f;
        #pragma unroll
        for (int j = 0; j < 8; j++) {
            float4 qv = *(const float4*)(Q + t * HPAD + j * 4);
            float4 kv = *(const float4*)(K + s * HPAD + j * 4);
            acc += qv.x * kv.x + qv.y * kv.y + qv.z * kv.z + qv.w * kv.w;
        }
        acc *= 0.17677669529663687f;   // 1/sqrt(32)
        bool m = (lastrow && (((t >> 2) >= 2) != ((s >> 2) >= 2))) ||
                 (lastcol && (((t & 3) >= 2) != ((s & 3) >= 2)));
        P[t * 17 + s] = m ? -1e30f : acc;
    }
    __syncwarp();

    // softmax per row (lanes 0..15)
    if (lane < 16) {
        float mx = -1e30f;
        #pragma unroll
        for (int s = 0; s < 16; s++) mx = fmaxf(mx, P[lane * 17 + s]);
        float sum = 0.f;
        #pragma unroll
        for (int s = 0; s < 16; s++) {
            float e = __expf(P[lane * 17 + s] - mx);
            P[lane * 17 + s] = e;
            sum += e;
        }
        float inv = 1.f / sum;
        #pragma unroll
        for (int s = 0; s < 16; s++) P[lane * 17 + s] *= inv;
    }
    __syncwarp();

    // out[t,e] = sum_s P[t,s] * V[s,e] ; lane -> (t = lane/2, 16 dims)
    {
        int t  = lane >> 1;
        int e0 = (lane & 1) * 16;
        float accv[16] = {};
        #pragma unroll
        for (int s = 0; s < 16; s++) {
            float p = P[t * 17 + s];
            #pragma unroll
            for (int j = 0; j < 4; j++) {
                float4 vv = *(const float4*)(V + s * HPAD + e0 + j * 4);
                accv[j * 4 + 0] += p * vv.x;
                accv[j * 4 + 1] += p * vv.y;
                accv[j * 4 + 2] += p * vv.z;
                accv[j * 4 + 3] += p * vv.w;
            }
        }
        // scatter: same row index as gather (shift+unshift cancel)
        float* op = out + (size_t)srow[t] * 256 + h * 32 + e0;
        #pragma unroll
        for (int j = 0; j < 4; j++)
            *(float4*)(op + j * 4) = make_float4(accv[j * 4 + 0], accv[j * 4 + 1],
                                                 accv[j * 4 + 2], accv[j * 4 + 3]);
    }
}

// ---------------------------------------------------------------------------

static const int ATTN_SMEM = (3 * 8 * 16 * HPAD + 8 * 16 * 17) * (int)sizeof(float); // 64000

extern "C" void kernel_launch(void* const* d_in, const int* in_sizes, int n_in,
                              void* d_out, int out_size)
{
    const float* x  = (const float*)d_in[0];   // [32, 3136, 256]
    const float* W  = (const float*)d_in[1];   // [256, 768]
    const float* bb = (const float*)d_in[2];   // [768]
    float* out = (float*)d_out;                // [32, 3136, 256]

    cudaFuncSetAttribute(win_attn, cudaFuncAttributeMaxDynamicSharedMemorySize, ATTN_SMEM);

    dim3 g(N_DIM / 128, M_TOTAL / 128);        // (6, 784)
    qkv_gemm<<<g, 256>>>(x, W, bb);
    win_attn<<<6272, 256, ATTN_SMEM>>>(out);
}

// round 2
// speedup vs baseline: 1.0001x; 1.0001x over previous
#include <cuda_runtime.h>
#include <math.h>

// ---------------------------------------------------------------------------
// ShiftedWindowMSA: B=32, H=W=56, D=256, heads=8, head_dim=32, ws=4, shift=2
//   1) qkv = x @ W + b              (100352 x 256) @ (256 x 768)
//   2) windowed attention within 4x4 windows (shift folded into gather index)
// ---------------------------------------------------------------------------

#define M_TOTAL  100352          // 32 * 3136
#define K_DIM    256
#define N_DIM    768

// scratch for qkv (static device allocation is the sanctioned scratch path)
__device__ float g_qkv[(size_t)M_TOTAL * N_DIM];

// ---------------------------------------------------------------------------
// Kernel 1: SGEMM  C[M,768] = A[M,256] * B[256,768] + bias
// BM=128 BN=128 BK=8, 256 threads, 8x8 micro-tile per thread.
// M,N,K all divide tile sizes exactly -> no bounds checks.
// ---------------------------------------------------------------------------
__global__ __launch_bounds__(256) void qkv_gemm(
    const float* __restrict__ A, const float* __restrict__ B,
    const float* __restrict__ bias)
{
    constexpr int BM = 128, BN = 128, BK = 8, TM = 8, TN = 8;
    __shared__ float As[BK][BM];
    __shared__ float Bs[BK][BN];

    const int tid = threadIdx.x;
    const int tx  = tid & 15;          // 0..15
    const int ty  = tid >> 4;          // 0..15
    const int bm  = blockIdx.y * BM;
    const int bn  = blockIdx.x * BN;

    // A tile loader: thread -> (row 0..127, 4-float chunk 0/4)
    const int arow = tid >> 1;
    const int acol = (tid & 1) * 4;
    // B tile loader: thread -> (row 0..7, col chunk)
    const int brow = tid >> 5;
    const int bcol = (tid & 31) * 4;

    const float* Aptr = A + (size_t)(bm + arow) * K_DIM + acol;
    const float* Bptr = B + (size_t)brow * N_DIM + bn + bcol;

    float acc[TM][TN] = {};

    for (int k0 = 0; k0 < K_DIM; k0 += BK) {
        float4 av = *(const float4*)(Aptr + k0);
        float4 bv = *(const float4*)(Bptr + (size_t)k0 * N_DIM);
        __syncthreads();   // previous compute done before overwrite
        As[acol + 0][arow] = av.x;
        As[acol + 1][arow] = av.y;
        As[acol + 2][arow] = av.z;
        As[acol + 3][arow] = av.w;
        *(float4*)&Bs[brow][bcol] = bv;
        __syncthreads();

        #pragma unroll
        for (int k = 0; k < BK; k++) {
            float a[TM], bb[TN];
            #pragma unroll
            for (int i = 0; i < TM; i++) a[i] = As[k][ty * TM + i];
            #pragma unroll
            for (int j = 0; j < TN; j++) bb[j] = Bs[k][tx * TN + j];
            #pragma unroll
            for (int i = 0; i < TM; i++)
                #pragma unroll
                for (int j = 0; j < TN; j++)
                    acc[i][j] += a[i] * bb[j];
        }
    }

    // epilogue: add bias, write to g_qkv
    #pragma unroll
    for (int i = 0; i < TM; i++) {
        size_t row = (size_t)(bm + ty * TM + i);
        float* cp = g_qkv + row * N_DIM + bn + tx * TN;
        #pragma unroll
        for (int j = 0; j < TN; j += 4) {
            int nn = bn + tx * TN + j;
            float4 v;
            v.x = acc[i][j + 0] + bias[nn + 0];
            v.y = acc[i][j + 1] + bias[nn + 1];
            v.z = acc[i][j + 2] + bias[nn + 2];
            v.w = acc[i][j + 3] + bias[nn + 3];
            *(float4*)(cp + j) = v;
        }
    }
}

// ---------------------------------------------------------------------------
// Kernel 2: windowed attention. One block per (batch, window). 8 warps = 8 heads.
// qkv row layout of the 768 dim: (head 8, e 32, comp 3) -> off = h*96 + e*3 + comp
// Shift folded into gather/scatter row index: (wi*4+r+2)%56, (wj*4+c+2)%56.
// ---------------------------------------------------------------------------
#define HPAD 36          // padded head_dim stride in smem (bank spread + float4 ok)

__global__ __launch_bounds__(256) void win_attn(float* __restrict__ out)
{
    extern __shared__ float sm[];
    float* sQ = sm;                      // 8*16*36 = 4608
    float* sK = sQ + 8 * 16 * HPAD;
    float* sV = sK + 8 * 16 * HPAD;
    float* sP = sV + 8 * 16 * HPAD;      // 8*16*17 = 2176
    __shared__ int srow[16];

    const int tid = threadIdx.x;
    const int blk = blockIdx.x;
    const int b   = blk / 196;
    const int rem = blk % 196;
    const int wi  = rem / 14;
    const int wj  = rem % 14;

    if (tid < 16) {
        int r = tid >> 2, c = tid & 3;
        int y = (wi * 4 + r + 2) % 56;   // shifted source row
        int x = (wj * 4 + c + 2) % 56;   // shifted source col
        srow[tid] = b * 3136 + y * 56 + x;
    }
    __syncthreads();

    // load 16 tokens x 768, de-interleave into Q/K/V [h][t][e]
    for (int i = tid; i < 16 * 192; i += 256) {
        int t = i / 192, q4 = i % 192;
        float4 v = *(const float4*)(g_qkv + (size_t)srow[t] * N_DIM + q4 * 4);
        float vals[4] = {v.x, v.y, v.z, v.w};
        #pragma unroll
        for (int j = 0; j < 4; j++) {
            int f = q4 * 4 + j;
            int h = f / 96;
            int rr = f - h * 96;
            int e = rr / 3;
            int comp = rr - e * 3;
            int idx = h * (16 * HPAD) + t * HPAD + e;
            if (comp == 0)      sQ[idx] = vals[j];
            else if (comp == 1) sK[idx] = vals[j];
            else                sV[idx] = vals[j];
        }
    }
    __syncthreads();

    const int h = tid >> 5, lane = tid & 31;
    const float* Q = sQ + h * (16 * HPAD);
    const float* K = sK + h * (16 * HPAD);
    const float* V = sV + h * (16 * HPAD);
    float* P = sP + h * (16 * 17);
    const bool lastrow = (wi == 13), lastcol = (wj == 13);

    // scores: each lane computes 8 (t,s) entries
    #pragma unroll
    for (int p = 0; p < 8; p++) {
        int flat = lane * 8 + p;
        int t = flat >> 4, s = flat & 15;
        float acc = 0.f;
        #pragma unroll
        for (int j = 0; j < 8; j++) {
            float4 qv = *(const float4*)(Q + t * HPAD + j * 4);
            float4 kv = *(const float4*)(K + s * HPAD + j * 4);
            acc += qv.x * kv.x + qv.y * kv.y + qv.z * kv.z + qv.w * kv.w;
        }
        acc *= 0.17677669529663687f;   // 1/sqrt(32)
        bool m = (lastrow && (((t >> 2) >= 2) != ((s >> 2) >= 2))) ||
                 (lastcol && (((t & 3) >= 2) != ((s & 3) >= 2)));
        P[t * 17 + s] = m ? -1e30f : acc;
    }
    __syncwarp();

    // softmax per row (lanes 0..15)
    if (lane < 16) {
        float mx = -1e30f;
        #pragma unroll
        for (int s = 0; s < 16; s++) mx = fmaxf(mx, P[lane * 17 + s]);
        float sum = 0.f;
        #pragma unroll
        for (int s = 0; s < 16; s++) {
            float e = __expf(P[lane * 17 + s] - mx);
            P[lane * 17 + s] = e;
            sum += e;
        }
        float inv = 1.f / sum;
        #pragma unroll
        for (int s = 0; s < 16; s++) P[lane * 17 + s] *= inv;
    }
    __syncwarp();

    // out[t,e] = sum_s P[t,s] * V[s,e] ; lane -> (t = lane/2, 16 dims)
    {
        int t  = lane >> 1;
        int e0 = (lane & 1) * 16;
        float accv[16] = {};
        #pragma unroll
        for (int s = 0; s < 16; s++) {
            float p = P[t * 17 + s];
            #pragma unroll
            for (int j = 0; j < 4; j++) {
                float4 vv = *(const float4*)(V + s * HPAD + e0 + j * 4);
                accv[j * 4 + 0] += p * vv.x;
                accv[j * 4 + 1] += p * vv.y;
                accv[j * 4 + 2] += p * vv.z;
                accv[j * 4 + 3] += p * vv.w;
            }
        }
        // scatter: same row index as gather (shift+unshift cancel)
        float* op = out + (size_t)srow[t] * 256 + h * 32 + e0;
        #pragma unroll
        for (int j = 0; j < 4; j++)
            *(float4*)(op + j * 4) = make_float4(accv[j * 4 + 0], accv[j * 4 + 1],
                                                 accv[j * 4 + 2], accv[j * 4 + 3]);
    }
}

// ---------------------------------------------------------------------------

static const int ATTN_SMEM = (3 * 8 * 16 * HPAD + 8 * 16 * 17) * (int)sizeof(float); // 64000

extern "C" void kernel_launch(void* const* d_in, const int* in_sizes, int n_in,
                              void* d_out, int out_size)
{
    const float* x  = (const float*)d_in[0];   // [32, 3136, 256]
    const float* W  = (const float*)d_in[1];   // [256, 768]
    const float* bb = (const float*)d_in[2];   // [768]
    float* out = (float*)d_out;                // [32, 3136, 256]

    cudaFuncSetAttribute(win_attn, cudaFuncAttributeMaxDynamicSharedMemorySize, ATTN_SMEM);

    dim3 g(N_DIM / 128, M_TOTAL / 128);        // (6, 784)
    qkv_gemm<<<g, 256>>>(x, W, bb);
    win_attn<<<6272, 256, ATTN_SMEM>>>(out);
}